// round 1
// baseline (speedup 1.0000x reference)
#include <cuda_runtime.h>
#include <stddef.h>

#define B_  32
#define T_  1024
#define D_  2048
#define U_  1024
#define M_  (B_*T_)

#define BM 128
#define BN 128
#define BK 16
#define NT (U_/BN)   // 8

// scratch (no device allocs allowed)
__device__ float g_qproj[B_*U_];
__device__ float g_score[B_*T_];

__device__ __forceinline__ float fast_tanh(float x) {
    float y; asm("tanh.approx.f32 %0, %1;" : "=f"(y) : "f"(x)); return y;
}

// ---------------------------------------------------------------------------
// K0: qproj[b][u] = sum_d query[b,d] * W2[d,u] + b2[u]
// grid = 32 (one block per b), 256 threads, 4 u's per thread (float4)
// ---------------------------------------------------------------------------
__global__ void qproj_kernel(const float* __restrict__ query,
                             const float* __restrict__ W2,
                             const float* __restrict__ b2) {
    int b  = blockIdx.x;
    int u4 = threadIdx.x;                 // covers u = u4*4 .. u4*4+3
    float4 acc = *(const float4*)&b2[u4*4];
    const float* q = query + (size_t)b * D_;
    #pragma unroll 8
    for (int d = 0; d < D_; d++) {
        float  qd = __ldg(&q[d]);
        float4 w  = *(const float4*)&W2[(size_t)d*U_ + u4*4];
        acc.x += qd*w.x; acc.y += qd*w.y; acc.z += qd*w.z; acc.w += qd*w.w;
    }
    *(float4*)&g_qproj[(size_t)b*U_ + u4*4] = acc;
}

// ---------------------------------------------------------------------------
// K1: fused GEMM + tanh + dot-V:
//   score[m] = bv + sum_n tanh( (values @ W1)[m,n] + b1[n] + qproj[b(m),n] ) * V[n]
// M = B*T = 32768, N = U = 1024, K = D = 2048.
// 256 blocks x 256 threads. Tile 128x128x16, 8x8 per-thread micro-tile,
// double-buffered smem, N-tiles looped inside the block with register
// score-partials (no atomics, no keys_proj materialization).
// ---------------------------------------------------------------------------
__global__ __launch_bounds__(256, 2)
void score_kernel(const float* __restrict__ values,
                  const float* __restrict__ W1,
                  const float* __restrict__ b1,
                  const float* __restrict__ Vvec,
                  const float* __restrict__ bvp) {
    __shared__ float As[2][BK][BM];        // A stored transposed: [k][m]
    __shared__ float Bs[2][BK][BN+4];      // [k][n] (+pad)
    __shared__ float red[BM][17];

    const int tid = threadIdx.x;
    const int tx  = tid & 15;              // n direction (8 cols each)
    const int ty  = tid >> 4;              // m direction (8 rows each)
    const int m0  = blockIdx.x * BM;       // tile never crosses batch boundary
    const int b   = m0 / T_;
    const float* qp = g_qproj + (size_t)b * U_;

    // global->smem load mapping: 512 float4 per tile side, 2 per thread
    const int af    = tid*2;
    const int arow0 = af >> 2,      ac0 = (af & 3) * 4;
    const int arow1 = (af+1) >> 2,  ac1 = ((af+1) & 3) * 4;
    const int bf    = tid*2;
    const int brow0 = bf >> 5,      bc0 = (bf & 31) * 4;
    const int brow1 = (bf+1) >> 5,  bc1 = ((bf+1) & 31) * 4;

    const float* Abase = values + (size_t)m0 * D_;

    float rowpart[8];
    #pragma unroll
    for (int i = 0; i < 8; i++) rowpart[i] = 0.f;

    for (int nt = 0; nt < NT; nt++) {
        const int n0 = nt * BN;
        float c[8][8];
        #pragma unroll
        for (int i = 0; i < 8; i++)
            #pragma unroll
            for (int j = 0; j < 8; j++) c[i][j] = 0.f;

        // preload k-tile 0 into buffer 0
        {
            float4 va0 = *(const float4*)&Abase[(size_t)arow0*D_ + ac0];
            float4 va1 = *(const float4*)&Abase[(size_t)arow1*D_ + ac1];
            As[0][ac0+0][arow0] = va0.x; As[0][ac0+1][arow0] = va0.y;
            As[0][ac0+2][arow0] = va0.z; As[0][ac0+3][arow0] = va0.w;
            As[0][ac1+0][arow1] = va1.x; As[0][ac1+1][arow1] = va1.y;
            As[0][ac1+2][arow1] = va1.z; As[0][ac1+3][arow1] = va1.w;
            float4 vb0 = *(const float4*)&W1[(size_t)brow0*U_ + n0 + bc0];
            float4 vb1 = *(const float4*)&W1[(size_t)brow1*U_ + n0 + bc1];
            *(float4*)&Bs[0][brow0][bc0] = vb0;
            *(float4*)&Bs[0][brow1][bc1] = vb1;
        }
        __syncthreads();

        int buf = 0;
        for (int kt = 0; kt < D_; kt += BK) {
            const int nxt = kt + BK;
            float4 va0, va1, vb0, vb1;
            const bool has = (nxt < D_);
            if (has) {
                const float* Ag = Abase + nxt;
                va0 = *(const float4*)&Ag[(size_t)arow0*D_ + ac0];
                va1 = *(const float4*)&Ag[(size_t)arow1*D_ + ac1];
                vb0 = *(const float4*)&W1[(size_t)(nxt+brow0)*U_ + n0 + bc0];
                vb1 = *(const float4*)&W1[(size_t)(nxt+brow1)*U_ + n0 + bc1];
            }
            #pragma unroll
            for (int kk = 0; kk < BK; kk++) {
                float4 a0 = *(float4*)&As[buf][kk][ty*8];
                float4 a1 = *(float4*)&As[buf][kk][ty*8+4];
                float4 b0 = *(float4*)&Bs[buf][kk][tx*8];
                float4 b1v = *(float4*)&Bs[buf][kk][tx*8+4];
                float a[8]  = {a0.x,a0.y,a0.z,a0.w,a1.x,a1.y,a1.z,a1.w};
                float bb[8] = {b0.x,b0.y,b0.z,b0.w,b1v.x,b1v.y,b1v.z,b1v.w};
                #pragma unroll
                for (int i = 0; i < 8; i++)
                    #pragma unroll
                    for (int j = 0; j < 8; j++)
                        c[i][j] += a[i] * bb[j];
            }
            if (has) {
                const int nb = buf ^ 1;
                As[nb][ac0+0][arow0] = va0.x; As[nb][ac0+1][arow0] = va0.y;
                As[nb][ac0+2][arow0] = va0.z; As[nb][ac0+3][arow0] = va0.w;
                As[nb][ac1+0][arow1] = va1.x; As[nb][ac1+1][arow1] = va1.y;
                As[nb][ac1+2][arow1] = va1.z; As[nb][ac1+3][arow1] = va1.w;
                *(float4*)&Bs[nb][brow0][bc0] = vb0;
                *(float4*)&Bs[nb][brow1][bc1] = vb1;
            }
            __syncthreads();
            buf ^= 1;
        }

        // epilogue: fold this N-tile into per-row score partials (registers only)
        #pragma unroll
        for (int j = 0; j < 8; j++) {
            const int n  = n0 + tx*8 + j;
            const float vj  = __ldg(&Vvec[n]);
            const float add = qp[n] + __ldg(&b1[n]);
            #pragma unroll
            for (int i = 0; i < 8; i++)
                rowpart[i] += fast_tanh(c[i][j] + add) * vj;
        }
    }

    // cross-thread reduction: 16 tx partials per row
    #pragma unroll
    for (int i = 0; i < 8; i++) red[ty*8 + i][tx] = rowpart[i];
    __syncthreads();
    if (tid < BM) {
        float s = 0.f;
        #pragma unroll
        for (int x = 0; x < 16; x++) s += red[tid][x];
        g_score[m0 + tid] = s + bvp[0];
    }
}

// ---------------------------------------------------------------------------
// K2: softmax over T per batch. One block per b, 1024 threads.
// ---------------------------------------------------------------------------
__global__ void softmax_kernel(float* __restrict__ out_w) {
    __shared__ float sh[32];
    __shared__ float bcast;
    const int b    = blockIdx.x;
    const int t    = threadIdx.x;
    const int lane = t & 31, wid = t >> 5;

    float s = g_score[(size_t)b*T_ + t];

    float m = s;
    #pragma unroll
    for (int o = 16; o; o >>= 1) m = fmaxf(m, __shfl_xor_sync(0xffffffffu, m, o));
    if (lane == 0) sh[wid] = m;
    __syncthreads();
    if (wid == 0) {
        float mm = sh[lane];
        #pragma unroll
        for (int o = 16; o; o >>= 1) mm = fmaxf(mm, __shfl_xor_sync(0xffffffffu, mm, o));
        if (lane == 0) bcast = mm;
    }
    __syncthreads();
    const float mx = bcast;

    float e = __expf(s - mx);
    float sum = e;
    #pragma unroll
    for (int o = 16; o; o >>= 1) sum += __shfl_xor_sync(0xffffffffu, sum, o);
    __syncthreads();                 // sh reuse
    if (lane == 0) sh[wid] = sum;
    __syncthreads();
    if (wid == 0) {
        float ss = sh[lane];
        #pragma unroll
        for (int o = 16; o; o >>= 1) ss += __shfl_xor_sync(0xffffffffu, ss, o);
        if (lane == 0) bcast = ss;
    }
    __syncthreads();

    out_w[(size_t)b*T_ + t] = e / bcast;
}

// ---------------------------------------------------------------------------
// K3: context[b,d] = sum_t w[b,t] * values[b,t,d]   (HBM-bound, 256 MB read)
// grid = B * (D/256), 256 threads.
// ---------------------------------------------------------------------------
__global__ void context_kernel(const float* __restrict__ values,
                               const float* __restrict__ w,
                               float* __restrict__ ctx) {
    __shared__ float ws[T_];
    const int b     = blockIdx.x >> 3;        // D_/256 = 8 chunks
    const int chunk = blockIdx.x & 7;
    const int d     = chunk*256 + threadIdx.x;

    for (int t = threadIdx.x; t < T_; t += 256)
        ws[t] = w[(size_t)b*T_ + t];
    __syncthreads();

    const float* vp = values + (size_t)b*T_*D_ + d;
    float acc = 0.f;
    #pragma unroll 8
    for (int t = 0; t < T_; t++)
        acc += ws[t] * vp[(size_t)t*D_];
    ctx[(size_t)b*D_ + d] = acc;
}

// ---------------------------------------------------------------------------
extern "C" void kernel_launch(void* const* d_in, const int* in_sizes, int n_in,
                              void* d_out, int out_size) {
    const float* query  = (const float*)d_in[0];
    const float* values = (const float*)d_in[1];
    const float* W1     = (const float*)d_in[2];
    const float* b1     = (const float*)d_in[3];
    const float* W2     = (const float*)d_in[4];
    const float* b2     = (const float*)d_in[5];
    const float* V      = (const float*)d_in[6];
    const float* bv     = (const float*)d_in[7];

    float* out = (float*)d_out;
    float* ctx = out;                   // (B, D)   = 65536 floats
    float* w   = out + B_*D_;           // (B, T, 1) = 32768 floats

    qproj_kernel  <<<B_,          256>>>(query, W2, b2);
    score_kernel  <<<M_/BM,       256>>>(values, W1, b1, V, bv);
    softmax_kernel<<<B_,          T_ >>>(w);
    context_kernel<<<B_*(D_/256), 256>>>(values, w, ctx);
}

// round 5
// speedup vs baseline: 1.0038x; 1.0038x over previous
#include <cuda_runtime.h>
#include <stddef.h>

#define B_  32
#define T_  1024
#define D_  2048
#define U_  1024
#define M_  (B_*T_)

#define BM 128
#define BN 128
#define BK 16
#define NT (U_/BN)   // 8

// scratch (no device allocs allowed)
__device__ float g_qproj[B_*U_];
__device__ float g_score[B_*T_];

__device__ __forceinline__ float fast_tanh(float x) {
    float y; asm("tanh.approx.f32 %0, %1;" : "=f"(y) : "f"(x)); return y;
}

// ---------------------------------------------------------------------------
// K0: qproj[b][u] = sum_d query[b,d] * W2[d,u] + b2[u]
// grid = 32 (one block per b), 256 threads, 4 u's per thread (float4)
// ---------------------------------------------------------------------------
__global__ void qproj_kernel(const float* __restrict__ query,
                             const float* __restrict__ W2,
                             const float* __restrict__ b2) {
    int b  = blockIdx.x;
    int u4 = threadIdx.x;                 // covers u = u4*4 .. u4*4+3
    float4 acc = *(const float4*)&b2[u4*4];
    const float* q = query + (size_t)b * D_;
    #pragma unroll 8
    for (int d = 0; d < D_; d++) {
        float  qd = __ldg(&q[d]);
        float4 w  = *(const float4*)&W2[(size_t)d*U_ + u4*4];
        acc.x += qd*w.x; acc.y += qd*w.y; acc.z += qd*w.z; acc.w += qd*w.w;
    }
    *(float4*)&g_qproj[(size_t)b*U_ + u4*4] = acc;
}

// ---------------------------------------------------------------------------
// K1: fused GEMM + tanh + dot-V:
//   score[m] = bv + sum_n tanh( (values @ W1)[m,n] + b1[n] + qproj[b(m),n] ) * V[n]
// M = B*T = 32768, N = U = 1024, K = D = 2048.
// 256 blocks x 256 threads. Tile 128x128x16, 8x8 per-thread micro-tile,
// double-buffered smem, N-tiles looped inside the block with register
// score-partials (no atomics, no keys_proj materialization).
// ---------------------------------------------------------------------------
__global__ __launch_bounds__(256, 2)
void score_kernel(const float* __restrict__ values,
                  const float* __restrict__ W1,
                  const float* __restrict__ b1,
                  const float* __restrict__ Vvec,
                  const float* __restrict__ bvp) {
    __shared__ float As[2][BK][BM];        // A stored transposed: [k][m]
    __shared__ float Bs[2][BK][BN+4];      // [k][n] (+pad)
    __shared__ float red[BM][17];

    const int tid = threadIdx.x;
    const int tx  = tid & 15;              // n direction (8 cols each)
    const int ty  = tid >> 4;              // m direction (8 rows each)
    const int m0  = blockIdx.x * BM;       // tile never crosses batch boundary
    const int b   = m0 / T_;
    const float* qp = g_qproj + (size_t)b * U_;

    // global->smem load mapping: 512 float4 per tile side, 2 per thread
    const int af    = tid*2;
    const int arow0 = af >> 2,      ac0 = (af & 3) * 4;
    const int arow1 = (af+1) >> 2,  ac1 = ((af+1) & 3) * 4;
    const int bf    = tid*2;
    const int brow0 = bf >> 5,      bc0 = (bf & 31) * 4;
    const int brow1 = (bf+1) >> 5,  bc1 = ((bf+1) & 31) * 4;

    const float* Abase = values + (size_t)m0 * D_;

    float rowpart[8];
    #pragma unroll
    for (int i = 0; i < 8; i++) rowpart[i] = 0.f;

    for (int nt = 0; nt < NT; nt++) {
        const int n0 = nt * BN;
        float c[8][8];
        #pragma unroll
        for (int i = 0; i < 8; i++)
            #pragma unroll
            for (int j = 0; j < 8; j++) c[i][j] = 0.f;

        // preload k-tile 0 into buffer 0
        {
            float4 va0 = *(const float4*)&Abase[(size_t)arow0*D_ + ac0];
            float4 va1 = *(const float4*)&Abase[(size_t)arow1*D_ + ac1];
            As[0][ac0+0][arow0] = va0.x; As[0][ac0+1][arow0] = va0.y;
            As[0][ac0+2][arow0] = va0.z; As[0][ac0+3][arow0] = va0.w;
            As[0][ac1+0][arow1] = va1.x; As[0][ac1+1][arow1] = va1.y;
            As[0][ac1+2][arow1] = va1.z; As[0][ac1+3][arow1] = va1.w;
            float4 vb0 = *(const float4*)&W1[(size_t)brow0*U_ + n0 + bc0];
            float4 vb1 = *(const float4*)&W1[(size_t)brow1*U_ + n0 + bc1];
            *(float4*)&Bs[0][brow0][bc0] = vb0;
            *(float4*)&Bs[0][brow1][bc1] = vb1;
        }
        __syncthreads();

        int buf = 0;
        for (int kt = 0; kt < D_; kt += BK) {
            const int nxt = kt + BK;
            float4 va0, va1, vb0, vb1;
            const bool has = (nxt < D_);
            if (has) {
                const float* Ag = Abase + nxt;
                va0 = *(const float4*)&Ag[(size_t)arow0*D_ + ac0];
                va1 = *(const float4*)&Ag[(size_t)arow1*D_ + ac1];
                vb0 = *(const float4*)&W1[(size_t)(nxt+brow0)*U_ + n0 + bc0];
                vb1 = *(const float4*)&W1[(size_t)(nxt+brow1)*U_ + n0 + bc1];
            }
            #pragma unroll
            for (int kk = 0; kk < BK; kk++) {
                float4 a0 = *(float4*)&As[buf][kk][ty*8];
                float4 a1 = *(float4*)&As[buf][kk][ty*8+4];
                float4 b0 = *(float4*)&Bs[buf][kk][tx*8];
                float4 b1v = *(float4*)&Bs[buf][kk][tx*8+4];
                float a[8]  = {a0.x,a0.y,a0.z,a0.w,a1.x,a1.y,a1.z,a1.w};
                float bb[8] = {b0.x,b0.y,b0.z,b0.w,b1v.x,b1v.y,b1v.z,b1v.w};
                #pragma unroll
                for (int i = 0; i < 8; i++)
                    #pragma unroll
                    for (int j = 0; j < 8; j++)
                        c[i][j] += a[i] * bb[j];
            }
            if (has) {
                const int nb = buf ^ 1;
                As[nb][ac0+0][arow0] = va0.x; As[nb][ac0+1][arow0] = va0.y;
                As[nb][ac0+2][arow0] = va0.z; As[nb][ac0+3][arow0] = va0.w;
                As[nb][ac1+0][arow1] = va1.x; As[nb][ac1+1][arow1] = va1.y;
                As[nb][ac1+2][arow1] = va1.z; As[nb][ac1+3][arow1] = va1.w;
                *(float4*)&Bs[nb][brow0][bc0] = vb0;
                *(float4*)&Bs[nb][brow1][bc1] = vb1;
            }
            __syncthreads();
            buf ^= 1;
        }

        // epilogue: fold this N-tile into per-row score partials (registers only)
        #pragma unroll
        for (int j = 0; j < 8; j++) {
            const int n  = n0 + tx*8 + j;
            const float vj  = __ldg(&Vvec[n]);
            const float add = qp[n] + __ldg(&b1[n]);
            #pragma unroll
            for (int i = 0; i < 8; i++)
                rowpart[i] += fast_tanh(c[i][j] + add) * vj;
        }
    }

    // cross-thread reduction: 16 tx partials per row
    #pragma unroll
    for (int i = 0; i < 8; i++) red[ty*8 + i][tx] = rowpart[i];
    __syncthreads();
    if (tid < BM) {
        float s = 0.f;
        #pragma unroll
        for (int x = 0; x < 16; x++) s += red[tid][x];
        g_score[m0 + tid] = s + bvp[0];
    }
}

// ---------------------------------------------------------------------------
// K2: softmax over T per batch. One block per b, 1024 threads.
// ---------------------------------------------------------------------------
__global__ void softmax_kernel(float* __restrict__ out_w) {
    __shared__ float sh[32];
    __shared__ float bcast;
    const int b    = blockIdx.x;
    const int t    = threadIdx.x;
    const int lane = t & 31, wid = t >> 5;

    float s = g_score[(size_t)b*T_ + t];

    float m = s;
    #pragma unroll
    for (int o = 16; o; o >>= 1) m = fmaxf(m, __shfl_xor_sync(0xffffffffu, m, o));
    if (lane == 0) sh[wid] = m;
    __syncthreads();
    if (wid == 0) {
        float mm = sh[lane];
        #pragma unroll
        for (int o = 16; o; o >>= 1) mm = fmaxf(mm, __shfl_xor_sync(0xffffffffu, mm, o));
        if (lane == 0) bcast = mm;
    }
    __syncthreads();
    const float mx = bcast;

    float e = __expf(s - mx);
    float sum = e;
    #pragma unroll
    for (int o = 16; o; o >>= 1) sum += __shfl_xor_sync(0xffffffffu, sum, o);
    __syncthreads();                 // sh reuse
    if (lane == 0) sh[wid] = sum;
    __syncthreads();
    if (wid == 0) {
        float ss = sh[lane];
        #pragma unroll
        for (int o = 16; o; o >>= 1) ss += __shfl_xor_sync(0xffffffffu, ss, o);
        if (lane == 0) bcast = ss;
    }
    __syncthreads();

    out_w[(size_t)b*T_ + t] = e / bcast;
}

// ---------------------------------------------------------------------------
// K3: context[b,d] = sum_t w[b,t] * values[b,t,d]   (HBM-bound, 256 MB read)
// grid = B * (D/256), 256 threads.
// ---------------------------------------------------------------------------
__global__ void context_kernel(const float* __restrict__ values,
                               const float* __restrict__ w,
                               float* __restrict__ ctx) {
    __shared__ float ws[T_];
    const int b     = blockIdx.x >> 3;        // D_/256 = 8 chunks
    const int chunk = blockIdx.x & 7;
    const int d     = chunk*256 + threadIdx.x;

    for (int t = threadIdx.x; t < T_; t += 256)
        ws[t] = w[(size_t)b*T_ + t];
    __syncthreads();

    const float* vp = values + (size_t)b*T_*D_ + d;
    float acc = 0.f;
    #pragma unroll 8
    for (int t = 0; t < T_; t++)
        acc += ws[t] * vp[(size_t)t*D_];
    ctx[(size_t)b*D_ + d] = acc;
}

// ---------------------------------------------------------------------------
extern "C" void kernel_launch(void* const* d_in, const int* in_sizes, int n_in,
                              void* d_out, int out_size) {
    const float* query  = (const float*)d_in[0];
    const float* values = (const float*)d_in[1];
    const float* W1     = (const float*)d_in[2];
    const float* b1     = (const float*)d_in[3];
    const float* W2     = (const float*)d_in[4];
    const float* b2     = (const float*)d_in[5];
    const float* V      = (const float*)d_in[6];
    const float* bv     = (const float*)d_in[7];

    float* out = (float*)d_out;
    float* ctx = out;                   // (B, D)   = 65536 floats
    float* w   = out + B_*D_;           // (B, T, 1) = 32768 floats

    qproj_kernel  <<<B_,          256>>>(query, W2, b2);
    score_kernel  <<<M_/BM,       256>>>(values, W1, b1, V, bv);
    softmax_kernel<<<B_,          T_ >>>(w);
    context_kernel<<<B_*(D_/256), 256>>>(values, w, ctx);
}

// round 8
// speedup vs baseline: 3.1597x; 3.1479x over previous
#include <cuda_runtime.h>
#include <cuda_bf16.h>
#include <cstdint>
#include <stddef.h>

#define B_  32
#define T_  1024
#define D_  2048
#define U_  1024
#define M_  (B_*T_)
#define NKC 64                 // k-chunks of 32 fp32

// ---- score kernel dynamic smem layout (offsets from 1024-aligned base) ----
#define OFF_BFA  0             // bf16 A tiles: 2 stages x 16384 (128 rows x [hi32|lo32] bf16)
#define OFF_BFB  32768         // bf16 B tiles: 2 stages x 32768 (256 rows x [hi32|lo32])
#define OFF_FPA  98304         // fp32 A staging: 2 stages x 18432 (128 rows x 144B padded)
#define OFF_QADD 135168        // 256 floats
#define OFF_VV   136192        // 256 floats
#define OFF_RED  137216        // 128x4 floats
#define SMEM_REQ 140288        // 139264 + align slack

// ---- scratch globals (no device allocs allowed) ----
__device__ unsigned char g_Bsw[(size_t)4*NKC*32768];   // 8MB pre-split/swizzled W1 image
__device__ float g_qpart[8*B_*U_];
__device__ float g_spart[4*M_];
__device__ float g_ctxpart[4*(size_t)B_*D_];

// ============================ helpers ============================
__device__ __forceinline__ uint32_t smem_u32(const void* p) {
    uint32_t a;
    asm("{ .reg .u64 t; cvta.to.shared.u64 t, %1; cvt.u32.u64 %0, t; }" : "=r"(a) : "l"(p));
    return a;
}
__device__ __forceinline__ float fast_tanh(float x) {
    float y; asm("tanh.approx.f32 %0, %1;" : "=f"(y) : "f"(x)); return y;
}
__device__ __forceinline__ unsigned pack_bf2(float a, float b) {
    __nv_bfloat16 ha = __float2bfloat16(a), hb = __float2bfloat16(b);
    return (unsigned)__bfloat16_as_ushort(ha) | ((unsigned)__bfloat16_as_ushort(hb) << 16);
}
__device__ __forceinline__ void split_pack(float a, float b, unsigned& hi, unsigned& lo) {
    __nv_bfloat16 ha = __float2bfloat16(a), hb = __float2bfloat16(b);
    hi = (unsigned)__bfloat16_as_ushort(ha) | ((unsigned)__bfloat16_as_ushort(hb) << 16);
    lo = pack_bf2(a - __bfloat162float(ha), b - __bfloat162float(hb));
}
__device__ __forceinline__ void cp_async16(uint32_t dst, const void* src) {
    asm volatile("cp.async.cg.shared.global [%0], [%1], 16;" :: "r"(dst), "l"(src));
}
#define CP_COMMIT() asm volatile("cp.async.commit_group;" ::: "memory")
#define CP_WAIT0()  asm volatile("cp.async.wait_group 0;" ::: "memory")
#define STS128(addr, r0, r1, r2, r3) \
    asm volatile("st.shared.v4.b32 [%0], {%1,%2,%3,%4};" \
                 :: "r"(addr), "r"(r0), "r"(r1), "r"(r2), "r"(r3) : "memory")
#define LDSM4(r, addr) \
    asm volatile("ldmatrix.sync.aligned.m8n8.x4.shared.b16 {%0,%1,%2,%3}, [%4];" \
                 : "=r"((r)[0]), "=r"((r)[1]), "=r"((r)[2]), "=r"((r)[3]) : "r"(addr))
#define MMA16816(d, a, b0, b1) \
    asm volatile("mma.sync.aligned.m16n8k16.row.col.f32.bf16.bf16.f32 " \
                 "{%0,%1,%2,%3}, {%4,%5,%6,%7}, {%8,%9}, {%0,%1,%2,%3};" \
                 : "+f"((d)[0]), "+f"((d)[1]), "+f"((d)[2]), "+f"((d)[3]) \
                 : "r"((a)[0]), "r"((a)[1]), "r"((a)[2]), "r"((a)[3]), "r"(b0), "r"(b1))

// ---------------------------------------------------------------------------
// K0: split+transpose W1 -> g_Bsw[nb 4][kc 64][tile 32KB]
// tile row n (0..255) = 128B: [hi k0..31 | lo k0..31] bf16, chunk-swizzled ^(n&7).
// grid (4, 64), 256 threads.
// ---------------------------------------------------------------------------
__global__ void w1split_kernel(const float* __restrict__ W1) {
    const int nb = blockIdx.x, kc = blockIdx.y, t = threadIdx.x;
    const int ng = nb*256 + t;
    float v[32];
    #pragma unroll
    for (int j = 0; j < 32; j++)
        v[j] = __ldg(&W1[(size_t)(kc*32 + j)*U_ + ng]);
    unsigned char* dst = g_Bsw + ((size_t)(nb*NKC + kc)*256 + t)*128;
    const int sx = t & 7;
    #pragma unroll
    for (int c = 0; c < 4; c++) {
        unsigned h[4], l[4];
        #pragma unroll
        for (int i = 0; i < 4; i++)
            split_pack(v[c*8 + 2*i], v[c*8 + 2*i + 1], h[i], l[i]);
        *(uint4*)(dst + ((c     ^ sx)*16)) = make_uint4(h[0], h[1], h[2], h[3]);
        *(uint4*)(dst + (((c+4) ^ sx)*16)) = make_uint4(l[0], l[1], l[2], l[3]);
    }
}

// ---------------------------------------------------------------------------
// K1: qproj partials: g_qpart[sl][b][u] = sum_{d in 256-slice} q[b,d]*W2[d,u] (+b2@sl0)
// grid (32, 8), 256 threads.
// ---------------------------------------------------------------------------
__global__ void qproj_part_kernel(const float* __restrict__ query,
                                  const float* __restrict__ W2,
                                  const float* __restrict__ b2) {
    const int b = blockIdx.x, sl = blockIdx.y;
    const int u4 = threadIdx.x;
    float4 acc = (sl == 0) ? *(const float4*)&b2[u4*4] : make_float4(0.f,0.f,0.f,0.f);
    const float* q = query + (size_t)b * D_;
    const int d0 = sl * 256;
    #pragma unroll 8
    for (int d = d0; d < d0 + 256; d++) {
        float  qd = __ldg(&q[d]);
        float4 w  = *(const float4*)&W2[(size_t)d*U_ + u4*4];
        acc.x += qd*w.x; acc.y += qd*w.y; acc.z += qd*w.z; acc.w += qd*w.w;
    }
    *(float4*)&g_qpart[(size_t)(sl*B_ + b)*U_ + u4*4] = acc;
}

// ---------------------------------------------------------------------------
// K2: fused bf16x3 HMMA GEMM + tanh + dot-V -> g_spart[nb][m]
// grid (256 mblk, 4 nblk), 512 threads (16 warps, 4m x 4n, warp tile 32x64).
// ---------------------------------------------------------------------------
__global__ __launch_bounds__(512, 1)
void score_kernel(const float* __restrict__ values,
                  const float* __restrict__ b1,
                  const float* __restrict__ Vvec) {
    extern __shared__ char smraw[];
    const uint32_t rb   = smem_u32(smraw);
    const uint32_t base = (rb + 1023u) & ~1023u;
    char* sm = smraw + (base - rb);

    const int tid = threadIdx.x;
    const int wid = tid >> 5, ln = tid & 31;
    const int wm  = wid >> 2, wn = wid & 3;
    const int mb  = blockIdx.x, nb = blockIdx.y;
    const int m0  = mb * 128, n0 = nb * 256;
    const int b   = m0 >> 10;

    float* qadd_s = (float*)(sm + OFF_QADD);
    float* vv_s   = (float*)(sm + OFF_VV);
    float* red    = (float*)(sm + OFF_RED);

    // qadd (qproj partial-sum + b1) and V for this 256-col slice
    if (tid < 256) {
        const int n = n0 + tid;
        float s = __ldg(&b1[n]);
        #pragma unroll
        for (int sl = 0; sl < 8; sl++) s += g_qpart[(size_t)(sl*B_ + b)*U_ + n];
        qadd_s[tid] = s;
        vv_s[tid]   = __ldg(&Vvec[n]);
    }

    const float* abase = values + (size_t)m0 * D_;
    const unsigned char* btiles = g_Bsw + (size_t)nb*NKC*32768;

    // ---- stage fill helper (lambda-free inline) ----
    // B: 2048 chunks of 16B linear; A fp32: 1024 chunks into 144B-padded rows.
    #define STAGE_FILL(stg, kc) do {                                              \
        const unsigned char* bt = btiles + (size_t)(kc)*32768;                    \
        const uint32_t bdst = base + OFF_BFB + (stg)*32768;                       \
        _Pragma("unroll")                                                         \
        for (int i = 0; i < 4; i++) {                                             \
            int g = tid + i*512;                                                  \
            cp_async16(bdst + g*16, bt + (size_t)g*16);                           \
        }                                                                         \
        const uint32_t adst = base + OFF_FPA + (stg)*18432;                       \
        _Pragma("unroll")                                                         \
        for (int i = 0; i < 2; i++) {                                             \
            int g = tid + i*512;                                                  \
            int r = g >> 3, c = g & 7;                                            \
            cp_async16(adst + r*144 + c*16,                                       \
                       abase + (size_t)r*D_ + (kc)*32 + c*4);                     \
        }                                                                         \
    } while (0)

    // accumulators: [mi 2][n8-tile 8][4]
    float acc[2][8][4];
    #pragma unroll
    for (int i = 0; i < 2; i++)
        #pragma unroll
        for (int j = 0; j < 8; j++)
            #pragma unroll
            for (int q = 0; q < 4; q++) acc[i][j][q] = 0.f;

    // ldmatrix address invariants
    const uint32_t sxs  = (uint32_t)(ln & 7) * 16;     // swizzle XOR (bytes)
    const uint32_t khfA = (uint32_t)(ln >> 4);         // A k-half from lane
    const uint32_t khfB = (uint32_t)((ln >> 3) & 1);   // B k-half from lane
    uint32_t rA[2], rB[4];
    #pragma unroll
    for (int mi = 0; mi < 2; mi++)
        rA[mi] = (uint32_t)(wm*32 + mi*16 + (ln & 15)) * 128;
    #pragma unroll
    for (int nt = 0; nt < 4; nt++)
        rB[nt] = (uint32_t)(wn*64 + nt*16 + (ln & 7) + ((ln >> 4) << 3)) * 128;

    // prologue
    STAGE_FILL(0, 0);
    CP_COMMIT();

    int stg = 0;
    const int r_cvt = tid >> 2, kq_cvt = tid & 3;

    for (int kc = 0; kc < NKC; kc++) {
        CP_WAIT0();
        __syncthreads();                       // stage stg: fpA+bfB ready; prior reads done

        // convert fp32 A (staging stg) -> bf16 hi/lo into bfA stage stg
        {
            const char* fa = sm + OFF_FPA + stg*18432 + r_cvt*144 + kq_cvt*32;
            float4 f0 = *(const float4*)fa;
            float4 f1 = *(const float4*)(fa + 16);
            unsigned h0,h1,h2,h3, l0,l1,l2,l3;
            split_pack(f0.x, f0.y, h0, l0);
            split_pack(f0.z, f0.w, h1, l1);
            split_pack(f1.x, f1.y, h2, l2);
            split_pack(f1.z, f1.w, h3, l3);
            const uint32_t ab = base + OFF_BFA + stg*16384 + r_cvt*128;
            const int rs = r_cvt & 7;
            STS128(ab + ((kq_cvt       ^ rs)*16), h0, h1, h2, h3);
            STS128(ab + (((kq_cvt + 4) ^ rs)*16), l0, l1, l2, l3);
        }

        if (kc + 1 < NKC) { STAGE_FILL(stg ^ 1, kc + 1); CP_COMMIT(); }
        __syncthreads();                       // bfA visible to all

        // ---- MMA block on stage stg ----
        const uint32_t A0 = base + OFF_BFA + stg*16384;
        const uint32_t B0 = base + OFF_BFB + stg*32768;
        #pragma unroll
        for (int s = 0; s < 2; s++) {
            uint32_t ah[2][4], al[2][4], bfr[4][4];
            const uint32_t cAh = (((uint32_t)s*2 + khfA)     * 16) ^ sxs;
            const uint32_t cAl = (((uint32_t)s*2 + khfA + 4) * 16) ^ sxs;
            #pragma unroll
            for (int mi = 0; mi < 2; mi++) {
                LDSM4(ah[mi], A0 + rA[mi] + cAh);
                LDSM4(al[mi], A0 + rA[mi] + cAl);
            }
            const uint32_t cBh = (((uint32_t)s*2 + khfB)     * 16) ^ sxs;
            const uint32_t cBl = (((uint32_t)s*2 + khfB + 4) * 16) ^ sxs;
            #pragma unroll
            for (int nt = 0; nt < 4; nt++) LDSM4(bfr[nt], B0 + rB[nt] + cBh);
            #pragma unroll
            for (int mi = 0; mi < 2; mi++)
                #pragma unroll
                for (int nt = 0; nt < 4; nt++) {
                    MMA16816(acc[mi][2*nt],   ah[mi], bfr[nt][0], bfr[nt][1]); // hi*hi
                    MMA16816(acc[mi][2*nt+1], ah[mi], bfr[nt][2], bfr[nt][3]);
                    MMA16816(acc[mi][2*nt],   al[mi], bfr[nt][0], bfr[nt][1]); // lo*hi
                    MMA16816(acc[mi][2*nt+1], al[mi], bfr[nt][2], bfr[nt][3]);
                }
            #pragma unroll
            for (int nt = 0; nt < 4; nt++) LDSM4(bfr[nt], B0 + rB[nt] + cBl);
            #pragma unroll
            for (int mi = 0; mi < 2; mi++)
                #pragma unroll
                for (int nt = 0; nt < 4; nt++) {
                    MMA16816(acc[mi][2*nt],   ah[mi], bfr[nt][0], bfr[nt][1]); // hi*lo
                    MMA16816(acc[mi][2*nt+1], ah[mi], bfr[nt][2], bfr[nt][3]);
                }
        }
        stg ^= 1;
    }

    // ---- epilogue: tanh(c + qadd)*V folded into per-row partials ----
    float racc[4] = {0.f, 0.f, 0.f, 0.f};     // [mi*2 + h], h = row+8h
    #pragma unroll
    for (int mi = 0; mi < 2; mi++)
        #pragma unroll
        for (int nj = 0; nj < 8; nj++) {
            const int nc = wn*64 + nj*8 + 2*(ln & 3);
            const float q0 = qadd_s[nc],   v0 = vv_s[nc];
            const float q1 = qadd_s[nc+1], v1 = vv_s[nc+1];
            const float* d = acc[mi][nj];
            racc[mi*2]   += fast_tanh(d[0] + q0)*v0 + fast_tanh(d[1] + q1)*v1;
            racc[mi*2+1] += fast_tanh(d[2] + q0)*v0 + fast_tanh(d[3] + q1)*v1;
        }
    #pragma unroll
    for (int off = 1; off <= 2; off <<= 1)
        #pragma unroll
        for (int i = 0; i < 4; i++)
            racc[i] += __shfl_xor_sync(0xffffffffu, racc[i], off);

    if ((ln & 3) == 0) {
        #pragma unroll
        for (int mi = 0; mi < 2; mi++)
            #pragma unroll
            for (int h = 0; h < 2; h++) {
                const int row = wm*32 + mi*16 + (ln >> 2) + 8*h;
                red[row*4 + wn] = racc[mi*2 + h];
            }
    }
    __syncthreads();
    if (tid < 128)
        g_spart[(size_t)nb*M_ + m0 + tid] =
            red[tid*4] + red[tid*4+1] + red[tid*4+2] + red[tid*4+3];
}

// ---------------------------------------------------------------------------
// K3: softmax over T per batch (sums the 4 n-block score partials).
// ---------------------------------------------------------------------------
__global__ void softmax_kernel(float* __restrict__ out_w) {
    __shared__ float sh[32];
    __shared__ float bcast;
    const int b = blockIdx.x, t = threadIdx.x;
    const int lane = t & 31, wd = t >> 5;
    const size_t idx = (size_t)b*T_ + t;

    float s = g_spart[idx] + g_spart[M_ + idx] + g_spart[2*(size_t)M_ + idx]
            + g_spart[3*(size_t)M_ + idx];

    float m = s;
    #pragma unroll
    for (int o = 16; o; o >>= 1) m = fmaxf(m, __shfl_xor_sync(0xffffffffu, m, o));
    if (lane == 0) sh[wd] = m;
    __syncthreads();
    if (wd == 0) {
        float mm = sh[lane];
        #pragma unroll
        for (int o = 16; o; o >>= 1) mm = fmaxf(mm, __shfl_xor_sync(0xffffffffu, mm, o));
        if (lane == 0) bcast = mm;
    }
    __syncthreads();
    const float mx = bcast;

    float e = __expf(s - mx);
    float sum = e;
    #pragma unroll
    for (int o = 16; o; o >>= 1) sum += __shfl_xor_sync(0xffffffffu, sum, o);
    __syncthreads();
    if (lane == 0) sh[wd] = sum;
    __syncthreads();
    if (wd == 0) {
        float ss = sh[lane];
        #pragma unroll
        for (int o = 16; o; o >>= 1) ss += __shfl_xor_sync(0xffffffffu, ss, o);
        if (lane == 0) bcast = ss;
    }
    __syncthreads();
    out_w[idx] = e / bcast;
}

// ---------------------------------------------------------------------------
// K4: context partials over t-slices of 256; grid (8, 4, 32), 256 threads.
// ---------------------------------------------------------------------------
__global__ void context_part_kernel(const float* __restrict__ values,
                                    const float* __restrict__ w) {
    __shared__ float ws[256];
    const int dc = blockIdx.x, ts = blockIdx.y, b = blockIdx.z;
    const int d  = dc*256 + threadIdx.x;
    ws[threadIdx.x] = w[(size_t)b*T_ + ts*256 + threadIdx.x];
    __syncthreads();
    const float* vp = values + ((size_t)b*T_ + ts*256)*D_ + d;
    float acc = 0.f;
    #pragma unroll 8
    for (int t = 0; t < 256; t++)
        acc += ws[t] * vp[(size_t)t*D_];
    g_ctxpart[(size_t)(ts*B_ + b)*D_ + d] = acc;
}

__global__ void context_reduce_kernel(float* __restrict__ ctx) {
    const size_t i = (size_t)blockIdx.x*256 + threadIdx.x;
    ctx[i] = g_ctxpart[i] + g_ctxpart[(size_t)B_*D_ + i]
           + g_ctxpart[(size_t)2*B_*D_ + i] + g_ctxpart[(size_t)3*B_*D_ + i];
}

// ---------------------------------------------------------------------------
extern "C" void kernel_launch(void* const* d_in, const int* in_sizes, int n_in,
                              void* d_out, int out_size) {
    const float* query  = (const float*)d_in[0];
    const float* values = (const float*)d_in[1];
    const float* W1     = (const float*)d_in[2];
    const float* b1     = (const float*)d_in[3];
    const float* W2     = (const float*)d_in[4];
    const float* b2     = (const float*)d_in[5];
    const float* V      = (const float*)d_in[6];
    // bv (d_in[7]) is a constant shift on scores: softmax-invariant, outputs unaffected.

    float* out = (float*)d_out;
    float* ctx = out;                   // (B, D)
    float* w   = out + B_*D_;           // (B, T, 1)

    cudaFuncSetAttribute(score_kernel, cudaFuncAttributeMaxDynamicSharedMemorySize, SMEM_REQ);

    w1split_kernel      <<<dim3(4, 64),    256>>>(W1);
    qproj_part_kernel   <<<dim3(B_, 8),    256>>>(query, W2, b2);
    score_kernel        <<<dim3(256, 4), 512, SMEM_REQ>>>(values, b1, V);
    softmax_kernel      <<<B_,            T_ >>>(w);
    context_part_kernel <<<dim3(8, 4, B_), 256>>>(values, w);
    context_reduce_kernel<<<(B_*D_)/256,   256>>>(ctx);
}